// round 8
// baseline (speedup 1.0000x reference)
#include <cuda_runtime.h>
#include <cuda_bf16.h>
#include <cstdint>

#define D 64
#define N_MAX 131072
#define E_MAX 2097152

// -------- device scratch --------
__device__ float g_H[N_MAX * D];
__device__ float g_A[N_MAX * D];
__device__ int   g_cnt[N_MAX];
__device__ float g_dinv[N_MAX];
__device__ int   g_rowtmp[N_MAX];
__device__ int   g_rowptr[N_MAX + 1];
__device__ int   g_cursor[N_MAX];
__device__ int   g_part[256];
__device__ int2  g_edge[E_MAX];   // {src col, norm bits}
__device__ int   g_elw;           // 1 = int32 edge index, 2 = int64

__device__ __forceinline__ uint32_t f2tf32(float f) {
    uint32_t r;
    asm("cvt.rna.tf32.f32 %0, %1;" : "=r"(r) : "f"(f));
    return r;
}

// -------- init + dtype probe --------
__global__ void k_init(const int* __restrict__ p, int n) {
    int i = blockIdx.x * blockDim.x + threadIdx.x;
    if (i < n) { g_cnt[i] = 0; g_cursor[i] = 0; }
    if (blockIdx.x == 0 && threadIdx.x == 0) {
        int nz = 0;
#pragma unroll
        for (int k = 0; k < 64; k++) nz |= p[2 * k + 1];
        g_elw = (nz == 0) ? 2 : 1;
    }
}

// -------- load helper: 8 edge endpoints starting at ofs --------
__device__ __forceinline__ void load8(const int* __restrict__ p, long long ofs,
                                      int e_rel, int avail, int elw, int* v) {
    // ofs: element offset of first item; avail: how many valid (<=8)
    if (elw == 1) {
        if (avail == 8 && ((ofs & 3) == 0)) {
            int4 a = *(const int4*)(p + ofs);
            int4 b = *(const int4*)(p + ofs + 4);
            v[0]=a.x; v[1]=a.y; v[2]=a.z; v[3]=a.w;
            v[4]=b.x; v[5]=b.y; v[6]=b.z; v[7]=b.w;
        } else {
            for (int i = 0; i < 8; i++) v[i] = (i < avail) ? p[ofs + i] : -1;
        }
    } else {
        const long long* q = (const long long*)p;
        if (avail == 8 && ((ofs & 1) == 0)) {
            longlong2 a = *(const longlong2*)(q + ofs);
            longlong2 b = *(const longlong2*)(q + ofs + 2);
            longlong2 c = *(const longlong2*)(q + ofs + 4);
            longlong2 d = *(const longlong2*)(q + ofs + 6);
            v[0]=(int)a.x; v[1]=(int)a.y; v[2]=(int)b.x; v[3]=(int)b.y;
            v[4]=(int)c.x; v[5]=(int)c.y; v[6]=(int)d.x; v[7]=(int)d.y;
        } else {
            for (int i = 0; i < 8; i++) v[i] = (i < avail) ? (int)q[ofs + i] : -1;
        }
    }
    (void)e_rel;
}

// -------- degree count: 8 edges/thread --------
__global__ void k_count(const int* __restrict__ p, int e, int n) {
    int base = (blockIdx.x * blockDim.x + threadIdx.x) * 8;
    if (base >= e) return;
    int elw = g_elw;
    int avail = min(8, e - base);
    int d[8];
    load8(p, (long long)e + base, base, avail, elw, d);
#pragma unroll
    for (int i = 0; i < 8; i++)
        if ((unsigned)d[i] < (unsigned)n) atomicAdd(&g_cnt[d[i]], 1);
}

// -------- scan A: warp-shuffle block scan + dinv --------
__global__ void __launch_bounds__(1024) k_scanA(int n) {
    __shared__ int wsum[32];
    int i = blockIdx.x * 1024 + threadIdx.x;
    int v = (i < n) ? g_cnt[i] : 0;
    if (i < n) g_dinv[i] = rsqrtf((float)(v + 1));
    int lane = threadIdx.x & 31, w = threadIdx.x >> 5;

    int x = v;  // inclusive warp scan
#pragma unroll
    for (int off = 1; off < 32; off <<= 1) {
        int t = __shfl_up_sync(0xffffffffu, x, off);
        if (lane >= off) x += t;
    }
    if (lane == 31) wsum[w] = x;
    __syncthreads();
    if (w == 0) {
        int s = wsum[lane];
        int t = s;
#pragma unroll
        for (int off = 1; off < 32; off <<= 1) {
            int u = __shfl_up_sync(0xffffffffu, t, off);
            if (lane >= off) t += u;
        }
        wsum[lane] = t - s;  // exclusive warp offsets
        if (lane == 31) g_part[blockIdx.x] = t;  // block total
    }
    __syncthreads();
    if (i < n) g_rowtmp[i] = x - v + wsum[w];
}

// -------- scan C: local scan of partials (scanB fused) --------
__global__ void k_scanC(int n, int e, int nb) {
    __shared__ int sh[128];
    __shared__ int ex[128];
    int t = threadIdx.x & 127;
    int v = (t < nb) ? g_part[t] : 0;
    sh[t] = v;
    __syncthreads();
#pragma unroll
    for (int off = 1; off < 128; off <<= 1) {
        int u = (t >= off) ? sh[t - off] : 0;
        __syncthreads();
        sh[t] += u;
        __syncthreads();
    }
    ex[t] = sh[t] - v;
    __syncthreads();

    int i = blockIdx.x * blockDim.x + threadIdx.x;
    if (i < n) g_rowptr[i] = g_rowtmp[i] + ex[i >> 10];
    if (i == 0) g_rowptr[n] = e;
}

// -------- CSR fill: 8 edges/thread, packed int2 payload --------
__global__ void k_fill(const int* __restrict__ p, int e, int n) {
    int base = (blockIdx.x * blockDim.x + threadIdx.x) * 8;
    if (base >= e) return;
    int elw = g_elw;
    int avail = min(8, e - base);
    int s[8], d[8];
    load8(p, (long long)base, base, avail, elw, s);
    load8(p, (long long)e + base, base, avail, elw, d);

    int pos[8];
#pragma unroll
    for (int i = 0; i < 8; i++) {
        pos[i] = -1;
        if ((unsigned)s[i] < (unsigned)n && (unsigned)d[i] < (unsigned)n)
            pos[i] = g_rowptr[d[i]] + atomicAdd(&g_cursor[d[i]], 1);
    }
#pragma unroll
    for (int i = 0; i < 8; i++) {
        if (pos[i] >= 0) {
            float nrm = g_dinv[s[i]] * g_dinv[d[i]];
            g_edge[pos[i]] = make_int2(s[i], __float_as_int(nrm));
        }
    }
}

// -------- GEMM: g_H[n,64] = A[n,64] @ W[64,64] via tf32 mma.sync --------
template <int SRC>
__global__ void __launch_bounds__(128) k_gemm(const float* __restrict__ Aext,
                                              const float* __restrict__ W, int n) {
    __shared__ float As[64][68];
    __shared__ float Ws[64][72];

    const float* A = (SRC == 0) ? Aext : (const float*)g_A;
    int tid = threadIdx.x;
    int rowbase = blockIdx.x * 64;

#pragma unroll
    for (int i = 0; i < 8; i++) {
        int idx = tid + i * 128;
        int r = idx >> 4;
        int f4 = idx & 15;
        float4 va = (rowbase + r < n)
            ? *(const float4*)(A + (size_t)(rowbase + r) * 64 + f4 * 4)
            : make_float4(0.f, 0.f, 0.f, 0.f);
        As[r][f4 * 4 + 0] = __uint_as_float(f2tf32(va.x));
        As[r][f4 * 4 + 1] = __uint_as_float(f2tf32(va.y));
        As[r][f4 * 4 + 2] = __uint_as_float(f2tf32(va.z));
        As[r][f4 * 4 + 3] = __uint_as_float(f2tf32(va.w));
        float4 vw = *(const float4*)(W + r * 64 + f4 * 4);
        Ws[r][f4 * 4 + 0] = __uint_as_float(f2tf32(vw.x));
        Ws[r][f4 * 4 + 1] = __uint_as_float(f2tf32(vw.y));
        Ws[r][f4 * 4 + 2] = __uint_as_float(f2tf32(vw.z));
        Ws[r][f4 * 4 + 3] = __uint_as_float(f2tf32(vw.w));
    }
    __syncthreads();

    int warp = tid >> 5, lane = tid & 31;
    int gid = lane >> 2;
    int tig = lane & 3;
    int ar0 = warp * 16 + gid;
    int ar1 = ar0 + 8;

    float acc[8][4];
#pragma unroll
    for (int t = 0; t < 8; t++)
#pragma unroll
        for (int c = 0; c < 4; c++) acc[t][c] = 0.f;

#pragma unroll
    for (int ks = 0; ks < 8; ks++) {
        int k0 = ks * 8;
        uint32_t a0 = __float_as_uint(As[ar0][k0 + tig]);
        uint32_t a1 = __float_as_uint(As[ar1][k0 + tig]);
        uint32_t a2 = __float_as_uint(As[ar0][k0 + tig + 4]);
        uint32_t a3 = __float_as_uint(As[ar1][k0 + tig + 4]);
#pragma unroll
        for (int nt = 0; nt < 8; nt++) {
            uint32_t b0 = __float_as_uint(Ws[k0 + tig][nt * 8 + gid]);
            uint32_t b1 = __float_as_uint(Ws[k0 + tig + 4][nt * 8 + gid]);
            asm volatile(
                "mma.sync.aligned.m16n8k8.row.col.f32.tf32.tf32.f32 "
                "{%0,%1,%2,%3}, {%4,%5,%6,%7}, {%8,%9}, {%0,%1,%2,%3};"
                : "+f"(acc[nt][0]), "+f"(acc[nt][1]), "+f"(acc[nt][2]), "+f"(acc[nt][3])
                : "r"(a0), "r"(a1), "r"(a2), "r"(a3), "r"(b0), "r"(b1));
        }
    }

    int row0 = rowbase + warp * 16 + gid;
    int row1 = row0 + 8;
#pragma unroll
    for (int nt = 0; nt < 8; nt++) {
        int col = nt * 8 + tig * 2;
        if (row0 < n)
            *(float2*)(g_H + (size_t)row0 * 64 + col) = make_float2(acc[nt][0], acc[nt][1]);
        if (row1 < n)
            *(float2*)(g_H + (size_t)row1 * 64 + col) = make_float2(acc[nt][2], acc[nt][3]);
    }
}

// -------- Aggregation (warp per node, float2, int2 edge payload) --------
template <int DSTOUT>
__global__ void k_agg(const float* __restrict__ bias, float* __restrict__ outext,
                      int n) {
    int gw = (blockIdx.x * blockDim.x + threadIdx.x) >> 5;
    int lane = threadIdx.x & 31;
    if (gw >= n) return;
    int i = gw;

    const float2* H2 = (const float2*)g_H;
    float di = g_dinv[i];
    float sn = di * di;
    float2 h = H2[i * 32 + lane];
    float2 acc = make_float2(h.x * sn, h.y * sn);

    int s = g_rowptr[i], e = g_rowptr[i + 1];
    for (int base = s; base < e; base += 32) {
        int m = min(32, e - base);
        int c = 0; float nv = 0.f;
        if (lane < m) {
            int2 ed = g_edge[base + lane];
            c = ed.x; nv = __int_as_float(ed.y);
        }
#pragma unroll 4
        for (int j = 0; j < m; j++) {
            int   cj = __shfl_sync(0xffffffffu, c, j);
            float nj = __shfl_sync(0xffffffffu, nv, j);
            float2 hh = __ldg(&H2[cj * 32 + lane]);
            acc.x += hh.x * nj;
            acc.y += hh.y * nj;
        }
    }
    float2 bb = ((const float2*)bias)[lane];
    acc.x = fmaxf(acc.x + bb.x, 0.f);
    acc.y = fmaxf(acc.y + bb.y, 0.f);
    float2* outp = (DSTOUT == 0) ? (float2*)g_A : (float2*)outext;
    outp[i * 32 + lane] = acc;
}

// -------- launch --------
extern "C" void kernel_launch(void* const* d_in, const int* in_sizes, int n_in,
                              void* d_out, int out_size) {
    const float* x  = (const float*)d_in[0];
    const int*   ei = (const int*)d_in[1];
    const float* W0 = (const float*)d_in[2];
    const float* b0 = (const float*)d_in[3];
    const float* W1 = (const float*)d_in[4];
    const float* b1 = (const float*)d_in[5];
    const float* W2 = (const float*)d_in[6];
    const float* b2 = (const float*)d_in[7];
    float* out = (float*)d_out;

    int n = in_sizes[0] / D;
    int e = in_sizes[1] / 2;
    int nb = (n + 1023) / 1024;
    int e8 = (e + 7) / 8;

    // lazy side-stream + events (host objects only; created before first capture)
    static cudaStream_t s2 = nullptr;
    static cudaEvent_t ev_fork = nullptr, ev_g0 = nullptr;
    if (!s2) {
        cudaStreamCreateWithFlags(&s2, cudaStreamNonBlocking);
        cudaEventCreateWithFlags(&ev_fork, cudaEventDisableTiming);
        cudaEventCreateWithFlags(&ev_g0, cudaEventDisableTiming);
    }

    int gemm_blocks = (n + 63) / 64;
    int agg_blocks  = (n + 7) / 8;

    // fork: GEMM0 (x @ W0) is independent of the CSR build
    cudaEventRecord(ev_fork, 0);
    cudaStreamWaitEvent(s2, ev_fork, 0);
    k_gemm<0><<<gemm_blocks, 128, 0, s2>>>(x, W0, n);
    cudaEventRecord(ev_g0, s2);

    // CSR build on main stream
    k_init <<<(n + 255) / 256, 256>>>(ei, n);
    k_count<<<(e8 + 255) / 256, 256>>>(ei, e, n);
    k_scanA<<<nb, 1024>>>(n);
    k_scanC<<<(n + 255) / 256, 256>>>(n, e, nb);
    k_fill <<<(e8 + 255) / 256, 256>>>(ei, e, n);

    // join, then layer pipeline
    cudaStreamWaitEvent(0, ev_g0, 0);
    k_agg<0> <<<agg_blocks, 256>>>(b0, nullptr, n);
    k_gemm<1><<<gemm_blocks, 128>>>(nullptr, W1, n);
    k_agg<0> <<<agg_blocks, 256>>>(b1, nullptr, n);
    k_gemm<1><<<gemm_blocks, 128>>>(nullptr, W2, n);
    k_agg<1> <<<agg_blocks, 256>>>(b2, out, n);
}